// round 3
// baseline (speedup 1.0000x reference)
#include <cuda_runtime.h>

// IF spiking neuron forward, non-align branch, T=4.
// x: [T*B, 1024, 3072] f32, thresh2/dtmem: [1024, 3072] f32
// out: [T*B, 1024, 3072] f32
//
// Per (b,i,j): mem = dtmem*thr; for t: mem += x_t; s = (mem>=thr)?thr:0; mem -= s; out_t = s.

#define T_STEPS 4
#define BATCH        8
#define FEAT_ELEMS   (1024 * 3072)          // 3,145,728
#define FEAT4        (FEAT_ELEMS / 4)       // 786,432 float4 per feature map
#define CHAIN4       (BATCH * FEAT4)        // 6,291,456 float4 chains per timestep

__global__ void __launch_bounds__(256) if_fwd_kernel(
    const float4* __restrict__ x,
    const float4* __restrict__ th,
    const float4* __restrict__ dt,
    float4* __restrict__ out)
{
    // x-dim covers the feature map (786,432 float4 = 3072 blocks of 256),
    // y-dim is the batch index (8). No modulo needed for the param index.
    const int f   = blockIdx.x * blockDim.x + threadIdx.x;   // 0 .. FEAT4-1
    const int b   = blockIdx.y;                              // 0 .. BATCH-1
    const int idx = b * FEAT4 + f;                           // chain index within one timestep

    const float4 thr = __ldg(&th[f]);
    const float4 d   = __ldg(&dt[f]);

    float4 mem;
    mem.x = d.x * thr.x;
    mem.y = d.y * thr.y;
    mem.z = d.z * thr.z;
    mem.w = d.w * thr.w;

    // Front-load all T independent global reads (MLP=4 LDG.128 per thread)
    float4 xv[T_STEPS];
#pragma unroll
    for (int t = 0; t < T_STEPS; t++) {
        xv[t] = x[(size_t)t * CHAIN4 + idx];
    }

#pragma unroll
    for (int t = 0; t < T_STEPS; t++) {
        float4 s;
        mem.x += xv[t].x;  s.x = (mem.x >= thr.x) ? thr.x : 0.0f;  mem.x -= s.x;
        mem.y += xv[t].y;  s.y = (mem.y >= thr.y) ? thr.y : 0.0f;  mem.y -= s.y;
        mem.z += xv[t].z;  s.z = (mem.z >= thr.z) ? thr.z : 0.0f;  mem.z -= s.z;
        mem.w += xv[t].w;  s.w = (mem.w >= thr.w) ? thr.w : 0.0f;  mem.w -= s.w;
        out[(size_t)t * CHAIN4 + idx] = s;
    }
}

extern "C" void kernel_launch(void* const* d_in, const int* in_sizes, int n_in,
                              void* d_out, int out_size)
{
    const float4* x  = (const float4*)d_in[0];   // [T*B, 1024, 3072]
    const float4* th = (const float4*)d_in[1];   // thresh2 [1024, 3072]
    const float4* dt = (const float4*)d_in[2];   // dtmem   [1024, 3072]
    float4*       o  = (float4*)d_out;

    dim3 threads(256, 1, 1);
    dim3 blocks(FEAT4 / 256, BATCH, 1);          // 3072 x 8 = 24,576 CTAs, no tail
    if_fwd_kernel<<<blocks, threads>>>(x, th, dt, o);
}

// round 4
// speedup vs baseline: 1.1698x; 1.1698x over previous
#include <cuda_runtime.h>

// IF spiking neuron forward, non-align branch, T=4.
// x: [T*B, 1024, 3072] f32, thresh2/dtmem: [1024, 3072] f32
// out: [T*B, 1024, 3072] f32
//
// Per (b,i,j): mem = dtmem*thr; for t: mem += x_t; s = (mem>=thr)?thr:0; mem -= s; out_t = s.
//
// R4 change vs R3: streaming cache hints (__ldcs on x, __stcs on out) so the
// 955 MB of stream traffic stops evicting the 25 MB of params from L2.
// R3 ncu showed 954 MB DRAM traffic vs 831 MB necessary (~123 MB of param
// re-fetches) at 6.89 TB/s.

#define T_STEPS 4
#define BATCH        8
#define FEAT_ELEMS   (1024 * 3072)          // 3,145,728
#define FEAT4        (FEAT_ELEMS / 4)       // 786,432 float4 per feature map
#define CHAIN4       (BATCH * FEAT4)        // 6,291,456 float4 chains per timestep

__global__ void __launch_bounds__(256) if_fwd_kernel(
    const float4* __restrict__ x,
    const float4* __restrict__ th,
    const float4* __restrict__ dt,
    float4* __restrict__ out)
{
    const int f   = blockIdx.x * blockDim.x + threadIdx.x;   // 0 .. FEAT4-1
    const int b   = blockIdx.y;                              // 0 .. BATCH-1
    const int idx = b * FEAT4 + f;                           // chain index within one timestep

    // Params: default policy -> stay L2-resident (8x reuse across batch)
    const float4 thr = __ldg(&th[f]);
    const float4 d   = __ldg(&dt[f]);

    float4 mem;
    mem.x = d.x * thr.x;
    mem.y = d.y * thr.y;
    mem.z = d.z * thr.z;
    mem.w = d.w * thr.w;

    // x: zero reuse -> streaming loads (evict-first), front-batched MLP=4
    float4 xv[T_STEPS];
#pragma unroll
    for (int t = 0; t < T_STEPS; t++) {
        xv[t] = __ldcs(&x[(size_t)t * CHAIN4 + idx]);
    }

#pragma unroll
    for (int t = 0; t < T_STEPS; t++) {
        float4 s;
        mem.x += xv[t].x;  s.x = (mem.x >= thr.x) ? thr.x : 0.0f;  mem.x -= s.x;
        mem.y += xv[t].y;  s.y = (mem.y >= thr.y) ? thr.y : 0.0f;  mem.y -= s.y;
        mem.z += xv[t].z;  s.z = (mem.z >= thr.z) ? thr.z : 0.0f;  mem.z -= s.z;
        mem.w += xv[t].w;  s.w = (mem.w >= thr.w) ? thr.w : 0.0f;  mem.w -= s.w;
        // out: zero reuse -> streaming store
        __stcs(&out[(size_t)t * CHAIN4 + idx], s);
    }
}

extern "C" void kernel_launch(void* const* d_in, const int* in_sizes, int n_in,
                              void* d_out, int out_size)
{
    const float4* x  = (const float4*)d_in[0];   // [T*B, 1024, 3072]
    const float4* th = (const float4*)d_in[1];   // thresh2 [1024, 3072]
    const float4* dt = (const float4*)d_in[2];   // dtmem   [1024, 3072]
    float4*       o  = (float4*)d_out;

    dim3 threads(256, 1, 1);
    dim3 blocks(FEAT4 / 256, BATCH, 1);          // 3072 x 8 = 24,576 CTAs, no tail
    if_fwd_kernel<<<blocks, threads>>>(x, th, dt, o);
}